// round 2
// baseline (speedup 1.0000x reference)
#include <cuda_runtime.h>
#include <cuda_bf16.h>
#include <math.h>

// Problem constants (see reference: N=64, T=512, D=512, H=512, fp32)
#define NB   64
#define TT   512
#define DD   512
#define HH   512
#define MM   (NB * TT)   // 32768 rows of the xWx GEMM

// ---------------------------------------------------------------------------
// Kernel A: xwx[m, h] = x[m, :] @ Wx[:, h] + b[h], written into d_out.
// Classic SMEM-tiled SGEMM: BM=128, BN=128, BK=8, 256 threads, 8x8 micro-tile.
// ---------------------------------------------------------------------------
#define BM 128
#define BN 128
#define BK 8

__global__ __launch_bounds__(256) void gemm_xwx_kernel(
    const float* __restrict__ X,    // [MM, DD]
    const float* __restrict__ Wx,   // [DD, HH]
    const float* __restrict__ bias, // [HH]
    float* __restrict__ out)        // [MM, HH]
{
    __shared__ float As[BK][BM];   // A tile, transposed (k-major)
    __shared__ float Bs[BK][BN];

    const int tid = threadIdx.x;
    const int m0 = blockIdx.y * BM;
    const int n0 = blockIdx.x * BN;

    // Load mapping: A tile is BM x BK = 1024 floats -> 256 float4 (1/thread)
    const int arow = tid >> 1;          // 0..127
    const int acol = (tid & 1) * 4;     // 0 or 4 (k offset)
    // B tile is BK x BN = 1024 floats -> 256 float4 (1/thread)
    const int brow = tid >> 5;          // 0..7 (k)
    const int bcol = (tid & 31) * 4;    // 0..124

    const int ty = tid >> 4;            // 0..15 -> rows ty*8..ty*8+7
    const int tx = tid & 15;            // 0..15 -> cols tx*8..tx*8+7

    float acc[8][8];
#pragma unroll
    for (int i = 0; i < 8; ++i)
#pragma unroll
        for (int j = 0; j < 8; ++j) acc[i][j] = 0.0f;

    for (int k0 = 0; k0 < DD; k0 += BK) {
        float4 av = *reinterpret_cast<const float4*>(
            X + (size_t)(m0 + arow) * DD + k0 + acol);
        float4 bv = *reinterpret_cast<const float4*>(
            Wx + (size_t)(k0 + brow) * HH + n0 + bcol);

        As[acol + 0][arow] = av.x;
        As[acol + 1][arow] = av.y;
        As[acol + 2][arow] = av.z;
        As[acol + 3][arow] = av.w;
        *reinterpret_cast<float4*>(&Bs[brow][bcol]) = bv;
        __syncthreads();

#pragma unroll
        for (int k = 0; k < BK; ++k) {
            float a[8], b[8];
            *reinterpret_cast<float4*>(a)     = *reinterpret_cast<const float4*>(&As[k][ty * 8]);
            *reinterpret_cast<float4*>(a + 4) = *reinterpret_cast<const float4*>(&As[k][ty * 8 + 4]);
            *reinterpret_cast<float4*>(b)     = *reinterpret_cast<const float4*>(&Bs[k][tx * 8]);
            *reinterpret_cast<float4*>(b + 4) = *reinterpret_cast<const float4*>(&Bs[k][tx * 8 + 4]);
#pragma unroll
            for (int i = 0; i < 8; ++i)
#pragma unroll
                for (int j = 0; j < 8; ++j)
                    acc[i][j] = fmaf(a[i], b[j], acc[i][j]);
        }
        __syncthreads();
    }

    // Epilogue: add bias, store (float4 x2 per row)
    float bb[8];
#pragma unroll
    for (int j = 0; j < 8; ++j) bb[j] = bias[n0 + tx * 8 + j];

#pragma unroll
    for (int i = 0; i < 8; ++i) {
        float* orow = out + (size_t)(m0 + ty * 8 + i) * HH + n0 + tx * 8;
        float4 v0 = make_float4(acc[i][0] + bb[0], acc[i][1] + bb[1],
                                acc[i][2] + bb[2], acc[i][3] + bb[3]);
        float4 v1 = make_float4(acc[i][4] + bb[4], acc[i][5] + bb[5],
                                acc[i][6] + bb[6], acc[i][7] + bb[7]);
        *reinterpret_cast<float4*>(orow)     = v0;
        *reinterpret_cast<float4*>(orow + 4) = v1;
    }
}

// ---------------------------------------------------------------------------
// Kernel B: sequential recurrence. One block per PAIR of batch rows (g=2 to
// halve Wh L2 traffic). 256 threads, each owns 2 output columns (float2 Wh
// loads). h kept in SMEM; xwx is read from d_out and overwritten in-place
// with h_t (read strictly precedes write within the same thread -> race-free).
// ---------------------------------------------------------------------------
__global__ __launch_bounds__(256) void rnn_recurrence_kernel(
    const float* __restrict__ h0,   // [NB, HH]
    const float* __restrict__ Wh,   // [HH, HH]
    float* __restrict__ out)        // [NB, TT, HH]: xwx in, h out
{
    const int tid = threadIdx.x;           // 0..255
    const int n0 = blockIdx.x * 2;         // batch pair
    const int j = tid * 2;                 // my two columns

    __shared__ float hs0[HH];
    __shared__ float hs1[HH];

    // init hidden state
    for (int i = tid; i < HH; i += 256) {
        hs0[i] = h0[(size_t)n0 * HH + i];
        hs1[i] = h0[(size_t)(n0 + 1) * HH + i];
    }
    __syncthreads();

    const float2* __restrict__ W2 = reinterpret_cast<const float2*>(Wh);
    float* out0 = out + (size_t)n0 * TT * HH;
    float* out1 = out + (size_t)(n0 + 1) * TT * HH;

    for (int t = 0; t < TT; ++t) {
        float2 a0 = *reinterpret_cast<const float2*>(out0 + (size_t)t * HH + j);
        float2 a1 = *reinterpret_cast<const float2*>(out1 + (size_t)t * HH + j);

#pragma unroll 8
        for (int k = 0; k < HH; ++k) {
            float2 w = W2[(size_t)k * (HH / 2) + tid];
            float hv0 = hs0[k];
            float hv1 = hs1[k];
            a0.x = fmaf(hv0, w.x, a0.x);
            a0.y = fmaf(hv0, w.y, a0.y);
            a1.x = fmaf(hv1, w.x, a1.x);
            a1.y = fmaf(hv1, w.y, a1.y);
        }

        float r00 = tanhf(a0.x);
        float r01 = tanhf(a0.y);
        float r10 = tanhf(a1.x);
        float r11 = tanhf(a1.y);

        __syncthreads();   // everyone done READING hs for step t
        hs0[j]     = r00;
        hs0[j + 1] = r01;
        hs1[j]     = r10;
        hs1[j + 1] = r11;
        *reinterpret_cast<float2*>(out0 + (size_t)t * HH + j) = make_float2(r00, r01);
        *reinterpret_cast<float2*>(out1 + (size_t)t * HH + j) = make_float2(r10, r11);
        __syncthreads();   // hs fully updated before step t+1 reads
    }
}

// ---------------------------------------------------------------------------
// Launch: inputs in metadata order: x, h0, Wx, Wh, b. Output (N,T,H) fp32.
// ---------------------------------------------------------------------------
extern "C" void kernel_launch(void* const* d_in, const int* in_sizes, int n_in,
                              void* d_out, int out_size) {
    const float* x  = (const float*)d_in[0];  // [NB, TT, DD]
    const float* h0 = (const float*)d_in[1];  // [NB, HH]
    const float* Wx = (const float*)d_in[2];  // [DD, HH]
    const float* Wh = (const float*)d_in[3];  // [HH, HH]
    const float* b  = (const float*)d_in[4];  // [HH]
    float* out = (float*)d_out;               // [NB, TT, HH]

    (void)in_sizes; (void)n_in; (void)out_size;

    // Stage 1: xwx = x @ Wx + b, written into out (used as scratch).
    dim3 gridA(HH / BN, MM / BM);   // (4, 256)
    gemm_xwx_kernel<<<gridA, 256>>>(x, Wx, b, out);

    // Stage 2: sequential recurrence, overwrites xwx with h_t in place.
    rnn_recurrence_kernel<<<NB / 2, 256>>>(h0, Wh, out);
}

// round 3
// speedup vs baseline: 6.7647x; 6.7647x over previous
#include <cuda_runtime.h>
#include <cuda_bf16.h>
#include <math.h>
#include <stdint.h>

// Problem constants: N=64, T=512, D=512, H=512, fp32
#define NB   64
#define TT   512
#define DD   512
#define HH   512
#define MM   (NB * TT)

// ---------------------------------------------------------------------------
// Kernel A: xwx[m, h] = x[m, :] @ Wx[:, h] + b[h], written into d_out.
// SMEM-tiled SGEMM: BM=128, BN=128, BK=8, 256 threads, 8x8 micro-tile.
// (unchanged from R1 — passed with rel_err 5e-7)
// ---------------------------------------------------------------------------
#define BM 128
#define BN 128
#define BK 8

__global__ __launch_bounds__(256) void gemm_xwx_kernel(
    const float* __restrict__ X,
    const float* __restrict__ Wx,
    const float* __restrict__ bias,
    float* __restrict__ out)
{
    __shared__ float As[BK][BM];
    __shared__ float Bs[BK][BN];

    const int tid = threadIdx.x;
    const int m0 = blockIdx.y * BM;
    const int n0 = blockIdx.x * BN;

    const int arow = tid >> 1;
    const int acol = (tid & 1) * 4;
    const int brow = tid >> 5;
    const int bcol = (tid & 31) * 4;

    const int ty = tid >> 4;
    const int tx = tid & 15;

    float acc[8][8];
#pragma unroll
    for (int i = 0; i < 8; ++i)
#pragma unroll
        for (int j = 0; j < 8; ++j) acc[i][j] = 0.0f;

    for (int k0 = 0; k0 < DD; k0 += BK) {
        float4 av = *reinterpret_cast<const float4*>(
            X + (size_t)(m0 + arow) * DD + k0 + acol);
        float4 bv = *reinterpret_cast<const float4*>(
            Wx + (size_t)(k0 + brow) * HH + n0 + bcol);

        As[acol + 0][arow] = av.x;
        As[acol + 1][arow] = av.y;
        As[acol + 2][arow] = av.z;
        As[acol + 3][arow] = av.w;
        *reinterpret_cast<float4*>(&Bs[brow][bcol]) = bv;
        __syncthreads();

#pragma unroll
        for (int k = 0; k < BK; ++k) {
            float a[8], b[8];
            *reinterpret_cast<float4*>(a)     = *reinterpret_cast<const float4*>(&As[k][ty * 8]);
            *reinterpret_cast<float4*>(a + 4) = *reinterpret_cast<const float4*>(&As[k][ty * 8 + 4]);
            *reinterpret_cast<float4*>(b)     = *reinterpret_cast<const float4*>(&Bs[k][tx * 8]);
            *reinterpret_cast<float4*>(b + 4) = *reinterpret_cast<const float4*>(&Bs[k][tx * 8 + 4]);
#pragma unroll
            for (int i = 0; i < 8; ++i)
#pragma unroll
                for (int j = 0; j < 8; ++j)
                    acc[i][j] = fmaf(a[i], b[j], acc[i][j]);
        }
        __syncthreads();
    }

    float bb[8];
#pragma unroll
    for (int j = 0; j < 8; ++j) bb[j] = bias[n0 + tx * 8 + j];

#pragma unroll
    for (int i = 0; i < 8; ++i) {
        float* orow = out + (size_t)(m0 + ty * 8 + i) * HH + n0 + tx * 8;
        float4 v0 = make_float4(acc[i][0] + bb[0], acc[i][1] + bb[1],
                                acc[i][2] + bb[2], acc[i][3] + bb[3]);
        float4 v1 = make_float4(acc[i][4] + bb[4], acc[i][5] + bb[5],
                                acc[i][6] + bb[6], acc[i][7] + bb[7]);
        *reinterpret_cast<float4*>(orow)     = v0;
        *reinterpret_cast<float4*>(orow + 4) = v1;
    }
}

// ---------------------------------------------------------------------------
// Kernel B: cluster-resident recurrence.
//   16 clusters x 8 CTAs. Cluster c owns batch rows [4c, 4c+4).
//   CTA rank r holds Wh[:, 64r : 64r+64) in SMEM (128 KB, loaded ONCE).
//   Per step: each CTA computes its 64-col slice of h_t for its 4 batch rows
//   (k split 8 ways across warps, reduced via SMEM), then broadcasts the
//   slice into all 8 CTAs' h buffer via st.shared::cluster; one
//   barrier.cluster per step. Wh never touches L2/HBM after the prologue.
// ---------------------------------------------------------------------------
#define CLUSTER       8
#define NCLUSTERS     (NB / 4)            // 16
#define NCTA          (NCLUSTERS * CLUSTER) // 128
#define BATCH_PER_CL  4
#define COLS_PER_CTA  (HH / CLUSTER)      // 64

#define WHS_ELEMS  (HH * COLS_PER_CTA)          // 32768 floats (128 KB)
#define HBUF_ELEMS (2 * BATCH_PER_CL * HH)      // 4096 floats (16 KB)
#define RED_ELEMS  (8 * BATCH_PER_CL * COLS_PER_CTA) // 2048 floats (8 KB)
#define RNN_SMEM_BYTES ((WHS_ELEMS + HBUF_ELEMS + RED_ELEMS) * 4)

__global__ __launch_bounds__(256, 1) __cluster_dims__(CLUSTER, 1, 1)
void rnn_cluster_kernel(const float* __restrict__ h0,
                        const float* __restrict__ Wh,
                        float* __restrict__ out)
{
    extern __shared__ float smem[];
    float* Whs  = smem;                     // [HH][COLS_PER_CTA]
    float* hbuf = smem + WHS_ELEMS;         // [2][BATCH_PER_CL][HH]
    float* red  = hbuf + HBUF_ELEMS;        // [8][BATCH_PER_CL][COLS_PER_CTA]

    const int tid = threadIdx.x;
    uint32_t rank;
    asm("mov.u32 %0, %%cluster_ctarank;" : "=r"(rank));
    const int cid = blockIdx.x / CLUSTER;
    const int b0  = cid * BATCH_PER_CL;

    // ---- Prologue: load Wh column slice (once) + init h buffer 0 ----
    {
        const int jg0 = rank * COLS_PER_CTA;
        for (int idx = tid; idx < WHS_ELEMS / 4; idx += 256) {
            int k  = idx >> 4;               // 16 float4 per k-row
            int c4 = (idx & 15) * 4;
            float4 v = *reinterpret_cast<const float4*>(
                &Wh[(size_t)k * HH + jg0 + c4]);
            *reinterpret_cast<float4*>(&Whs[k * COLS_PER_CTA + c4]) = v;
        }
    }
    for (int idx = tid; idx < BATCH_PER_CL * HH; idx += 256) {
        hbuf[idx] = h0[(size_t)b0 * HH + idx];
    }
    __syncthreads();
    asm volatile("barrier.cluster.arrive.aligned;\n\t"
                 "barrier.cluster.wait.aligned;" ::: "memory");

    // compute mapping: warp-uniform k-split, conflict-free float2 Wh loads
    const int c2 = tid & 31;                // col pair index (cols 2*c2, 2*c2+1)
    const int kq = tid >> 5;                // k-split 0..7 (one per warp)
    // final-stage mapping: one output per thread
    const int fb = tid >> 6;                // batch 0..3
    const int fc = tid & 63;                // local col
    const int jg = rank * COLS_PER_CTA + fc;
    float* outp = out + ((size_t)(b0 + fb) * TT) * HH + jg;

    uint32_t smem_u32;
    {
        uint32_t a;
        asm("{ .reg .u64 t; cvta.to.shared.u64 t, %1; cvt.u32.u64 %0, t; }"
            : "=r"(a) : "l"(smem));
        smem_u32 = a;
    }
    const uint32_t hbuf_u32 = smem_u32 + WHS_ELEMS * 4;

    const int kbase = kq * 64;
    const float* wp = Whs + (size_t)kbase * COLS_PER_CTA + 2 * c2;

    int cur = 0;
    for (int t = 0; t < TT; ++t) {
        // prefetch my xwx value for this step (consumed after the reduce)
        float xw = __ldg(outp + (size_t)t * HH);

        const float* hc = hbuf + cur * (BATCH_PER_CL * HH);
        float a00 = 0.f, a01 = 0.f, a10 = 0.f, a11 = 0.f;
        float a20 = 0.f, a21 = 0.f, a30 = 0.f, a31 = 0.f;

#pragma unroll 2
        for (int kk = 0; kk < 64; kk += 4) {
            const int k = kbase + kk;
            float4 h0v = *reinterpret_cast<const float4*>(&hc[0 * HH + k]);
            float4 h1v = *reinterpret_cast<const float4*>(&hc[1 * HH + k]);
            float4 h2v = *reinterpret_cast<const float4*>(&hc[2 * HH + k]);
            float4 h3v = *reinterpret_cast<const float4*>(&hc[3 * HH + k]);
            float2 w0 = *reinterpret_cast<const float2*>(&wp[(kk + 0) * COLS_PER_CTA]);
            float2 w1 = *reinterpret_cast<const float2*>(&wp[(kk + 1) * COLS_PER_CTA]);
            float2 w2 = *reinterpret_cast<const float2*>(&wp[(kk + 2) * COLS_PER_CTA]);
            float2 w3 = *reinterpret_cast<const float2*>(&wp[(kk + 3) * COLS_PER_CTA]);

            a00 = fmaf(h0v.x, w0.x, a00); a01 = fmaf(h0v.x, w0.y, a01);
            a10 = fmaf(h1v.x, w0.x, a10); a11 = fmaf(h1v.x, w0.y, a11);
            a20 = fmaf(h2v.x, w0.x, a20); a21 = fmaf(h2v.x, w0.y, a21);
            a30 = fmaf(h3v.x, w0.x, a30); a31 = fmaf(h3v.x, w0.y, a31);

            a00 = fmaf(h0v.y, w1.x, a00); a01 = fmaf(h0v.y, w1.y, a01);
            a10 = fmaf(h1v.y, w1.x, a10); a11 = fmaf(h1v.y, w1.y, a11);
            a20 = fmaf(h2v.y, w1.x, a20); a21 = fmaf(h2v.y, w1.y, a21);
            a30 = fmaf(h3v.y, w1.x, a30); a31 = fmaf(h3v.y, w1.y, a31);

            a00 = fmaf(h0v.z, w2.x, a00); a01 = fmaf(h0v.z, w2.y, a01);
            a10 = fmaf(h1v.z, w2.x, a10); a11 = fmaf(h1v.z, w2.y, a11);
            a20 = fmaf(h2v.z, w2.x, a20); a21 = fmaf(h2v.z, w2.y, a21);
            a30 = fmaf(h3v.z, w2.x, a30); a31 = fmaf(h3v.z, w2.y, a31);

            a00 = fmaf(h0v.w, w3.x, a00); a01 = fmaf(h0v.w, w3.y, a01);
            a10 = fmaf(h1v.w, w3.x, a10); a11 = fmaf(h1v.w, w3.y, a11);
            a20 = fmaf(h2v.w, w3.x, a20); a21 = fmaf(h2v.w, w3.y, a21);
            a30 = fmaf(h3v.w, w3.x, a30); a31 = fmaf(h3v.w, w3.y, a31);
        }

        // partial sums -> smem reduce buffer: red[kq][b][c]
        {
            float2* r2 = reinterpret_cast<float2*>(red);
            const int base = (kq * BATCH_PER_CL) * (COLS_PER_CTA / 2) + c2;
            r2[base + 0 * (COLS_PER_CTA / 2)] = make_float2(a00, a01);
            r2[base + 1 * (COLS_PER_CTA / 2)] = make_float2(a10, a11);
            r2[base + 2 * (COLS_PER_CTA / 2)] = make_float2(a20, a21);
            r2[base + 3 * (COLS_PER_CTA / 2)] = make_float2(a30, a31);
        }
        __syncthreads();

        // final: 8-way reduce + bias(xwx) + tanh
        float s = xw;
#pragma unroll
        for (int q = 0; q < 8; ++q)
            s += red[(q * BATCH_PER_CL + fb) * COLS_PER_CTA + fc];
        float r = tanhf(s);

        // write output
        outp[(size_t)t * HH] = r;

        // broadcast my h value into every CTA's next-h buffer (incl. self)
        const int nxt = cur ^ 1;
        const uint32_t dst =
            hbuf_u32 + (uint32_t)((nxt * BATCH_PER_CL + fb) * HH + jg) * 4;
#pragma unroll
        for (int p = 0; p < CLUSTER; ++p) {
            uint32_t ra;
            asm volatile("mapa.shared::cluster.u32 %0, %1, %2;"
                         : "=r"(ra) : "r"(dst), "r"(p));
            asm volatile("st.shared::cluster.f32 [%0], %1;"
                         :: "r"(ra), "f"(r) : "memory");
        }

        // release stores to peers / acquire peers' stores; also acts as CTA sync
        asm volatile("barrier.cluster.arrive.aligned;\n\t"
                     "barrier.cluster.wait.aligned;" ::: "memory");
        cur = nxt;
    }
}

// ---------------------------------------------------------------------------
// Launch: inputs in metadata order: x, h0, Wx, Wh, b. Output (N,T,H) fp32.
// ---------------------------------------------------------------------------
extern "C" void kernel_launch(void* const* d_in, const int* in_sizes, int n_in,
                              void* d_out, int out_size) {
    const float* x  = (const float*)d_in[0];
    const float* h0 = (const float*)d_in[1];
    const float* Wx = (const float*)d_in[2];
    const float* Wh = (const float*)d_in[3];
    const float* b  = (const float*)d_in[4];
    float* out = (float*)d_out;

    (void)in_sizes; (void)n_in; (void)out_size;

    // Stage 1: xwx = x @ Wx + b, into out (scratch).
    dim3 gridA(HH / BN, MM / BM);
    gemm_xwx_kernel<<<gridA, 256>>>(x, Wx, b, out);

    // Stage 2: cluster-resident recurrence (Wh loaded into SMEM once).
    cudaFuncSetAttribute(rnn_cluster_kernel,
                         cudaFuncAttributeMaxDynamicSharedMemorySize,
                         RNN_SMEM_BYTES);
    rnn_cluster_kernel<<<NCTA, 256, RNN_SMEM_BYTES>>>(h0, Wh, out);
}

// round 5
// speedup vs baseline: 8.1550x; 1.2055x over previous
#include <cuda_runtime.h>
#include <cuda_bf16.h>
#include <math.h>
#include <stdint.h>

// Problem constants: N=64, T=512, D=512, H=512, fp32
#define NB   64
#define TT   512
#define DD   512
#define HH   512
#define MM   (NB * TT)

// ---------------------------------------------------------------------------
// f32x2 packed-math helpers (Blackwell FFMA2 path — only reachable via PTX)
// ---------------------------------------------------------------------------
__device__ __forceinline__ void ffma2(unsigned long long& acc,
                                      unsigned long long a,
                                      unsigned long long b) {
    asm("fma.rn.f32x2 %0, %1, %2, %0;" : "+l"(acc) : "l"(a), "l"(b));
}
__device__ __forceinline__ unsigned long long add2(unsigned long long a,
                                                   unsigned long long b) {
    unsigned long long r;
    asm("add.rn.f32x2 %0, %1, %2;" : "=l"(r) : "l"(a), "l"(b));
    return r;
}
__device__ __forceinline__ unsigned long long pack_dup(float v) {
    unsigned long long r;
    unsigned u = __float_as_uint(v);
    asm("mov.b64 %0, {%1, %1};" : "=l"(r) : "r"(u));
    return r;
}

// ---------------------------------------------------------------------------
// Kernel A: xwx[m, h] = x[m, :] @ Wx[:, h] + b[h]  (written into d_out).
// SMEM-tiled SGEMM, BM=BN=128, BK=8, 256 threads, 8x8 micro-tile, but with
// f32x2 packed FMA: A stored DUPLICATED in SMEM ({a,a}) so each FFMA2 needs
// zero pack instructions; B column pairs are natively packed.
// ---------------------------------------------------------------------------
#define BM 128
#define BN 128
#define BK 8

__global__ __launch_bounds__(256) void gemm_xwx_kernel(
    const float* __restrict__ X,
    const float* __restrict__ Wx,
    const float* __restrict__ bias,
    float* __restrict__ out)
{
    __shared__ float2 Asd[BK][BM];   // duplicated A: {a, a}
    __shared__ float  Bs[BK][BN];

    const int tid = threadIdx.x;
    const int m0 = blockIdx.y * BM;
    const int n0 = blockIdx.x * BN;

    const int arow = tid >> 1;
    const int acol = (tid & 1) * 4;
    const int brow = tid >> 5;
    const int bcol = (tid & 31) * 4;

    const int ty = tid >> 4;
    const int tx = tid & 15;

    unsigned long long acc2[8][4];
#pragma unroll
    for (int i = 0; i < 8; ++i)
#pragma unroll
        for (int j = 0; j < 4; ++j) acc2[i][j] = 0ULL;

    for (int k0 = 0; k0 < DD; k0 += BK) {
        float4 av = *reinterpret_cast<const float4*>(
            X + (size_t)(m0 + arow) * DD + k0 + acol);
        float4 bv = *reinterpret_cast<const float4*>(
            Wx + (size_t)(k0 + brow) * HH + n0 + bcol);

        Asd[acol + 0][arow] = make_float2(av.x, av.x);
        Asd[acol + 1][arow] = make_float2(av.y, av.y);
        Asd[acol + 2][arow] = make_float2(av.z, av.z);
        Asd[acol + 3][arow] = make_float2(av.w, av.w);
        *reinterpret_cast<float4*>(&Bs[brow][bcol]) = bv;
        __syncthreads();

#pragma unroll
        for (int k = 0; k < BK; ++k) {
            unsigned long long a2[8], b2[4];
            ulonglong2 t0 = *reinterpret_cast<const ulonglong2*>(&Bs[k][tx * 8]);
            ulonglong2 t1 = *reinterpret_cast<const ulonglong2*>(&Bs[k][tx * 8 + 4]);
            b2[0] = t0.x; b2[1] = t0.y; b2[2] = t1.x; b2[3] = t1.y;
#pragma unroll
            for (int i = 0; i < 8; ++i)
                a2[i] = *reinterpret_cast<const unsigned long long*>(&Asd[k][ty * 8 + i]);
#pragma unroll
            for (int i = 0; i < 8; ++i)
#pragma unroll
                for (int j = 0; j < 4; ++j)
                    ffma2(acc2[i][j], a2[i], b2[j]);
        }
        __syncthreads();
    }

    // Epilogue: packed bias add + packed stores
    unsigned long long bb2[4];
    {
        ulonglong2 t0 = *reinterpret_cast<const ulonglong2*>(bias + n0 + tx * 8);
        ulonglong2 t1 = *reinterpret_cast<const ulonglong2*>(bias + n0 + tx * 8 + 4);
        bb2[0] = t0.x; bb2[1] = t0.y; bb2[2] = t1.x; bb2[3] = t1.y;
    }
#pragma unroll
    for (int i = 0; i < 8; ++i) {
        float* orow = out + (size_t)(m0 + ty * 8 + i) * HH + n0 + tx * 8;
        ulonglong2 v0, v1;
        v0.x = add2(acc2[i][0], bb2[0]);
        v0.y = add2(acc2[i][1], bb2[1]);
        v1.x = add2(acc2[i][2], bb2[2]);
        v1.y = add2(acc2[i][3], bb2[3]);
        *reinterpret_cast<ulonglong2*>(orow)     = v0;
        *reinterpret_cast<ulonglong2*>(orow + 4) = v1;
    }
}

// ---------------------------------------------------------------------------
// Kernel B: cluster recurrence, Wh REGISTER-resident.
//   16 clusters x 8 CTAs, 512 threads/CTA. Cluster owns 4 batch rows; CTA
//   rank r owns output columns [64r, 64r+64).
//   Thread (kq = tid>>4, cq = tid&15) holds Wh[kbase..kbase+16)[4cq..4cq+4)
//   in 32 packed f32x2 registers (loaded from GMEM once). Per step it
//   computes 4 batch x 4 col partial dots with FFMA2, partials reduced via
//   SMEM (32-way k-split), tanh.approx, result broadcast to all 8 CTAs' h
//   buffer via st.shared::cluster, one cluster barrier per step.
// ---------------------------------------------------------------------------
#define CLUSTER       8
#define NCTA          128          // 16 clusters x 8
#define BATCH_PER_CL  4
#define COLS_PER_CTA  64

#define HBUF_ELEMS (2 * BATCH_PER_CL * HH)        // 4096 floats (16 KB)
#define RED_ELEMS  (32 * BATCH_PER_CL * COLS_PER_CTA) // 8192 floats (32 KB)
#define RNN_SMEM_BYTES ((HBUF_ELEMS + RED_ELEMS) * 4) // 48 KB

__global__ __launch_bounds__(512, 1) __cluster_dims__(CLUSTER, 1, 1)
void rnn_cluster_kernel(const float* __restrict__ h0,
                        const float* __restrict__ Wh,
                        float* __restrict__ out)
{
    extern __shared__ float smem[];
    float* hbuf = smem;                 // [2][4][HH]
    float* red  = smem + HBUF_ELEMS;    // [32][4][64]

    const int tid = threadIdx.x;
    uint32_t rank;
    asm("mov.u32 %0, %%cluster_ctarank;" : "=r"(rank));
    const int cid = blockIdx.x >> 3;
    const int b0  = cid * BATCH_PER_CL;

    const int kq    = tid >> 4;          // 0..31
    const int cq    = tid & 15;          // 0..15
    const int kbase = kq * 16;
    const int jg0   = (int)rank * COLS_PER_CTA + cq * 4;

    // ---- Wh slice -> registers (once) ----
    unsigned long long w01[16], w23[16];
#pragma unroll
    for (int kk = 0; kk < 16; ++kk) {
        ulonglong2 v = *reinterpret_cast<const ulonglong2*>(
            Wh + (size_t)(kbase + kk) * HH + jg0);
        w01[kk] = v.x;
        w23[kk] = v.y;
    }

    // ---- init h (phase 0) ----
    for (int idx = tid; idx < BATCH_PER_CL * HH; idx += 512)
        hbuf[idx] = h0[(size_t)b0 * HH + idx];
    __syncthreads();
    asm volatile("barrier.cluster.arrive.aligned;\n\t"
                 "barrier.cluster.wait.aligned;" ::: "memory");

    // ---- output-stage mapping (threads < 256) ----
    const int fb = (tid >> 6) & 3;       // batch 0..3
    const int fc = tid & 63;             // local col
    const int jg = (int)rank * COLS_PER_CTA + fc;
    float* outp = out + ((size_t)(b0 + fb) * TT) * HH + jg;

    // peer hbuf base addresses (mapa once)
    uint32_t hbuf_u32;
    asm("{ .reg .u64 t; cvta.to.shared.u64 t, %1; cvt.u32.u64 %0, t; }"
        : "=r"(hbuf_u32) : "l"(smem));
    uint32_t rb[CLUSTER];
#pragma unroll
    for (int p = 0; p < CLUSTER; ++p)
        asm("mapa.shared::cluster.u32 %0, %1, %2;"
            : "=r"(rb[p]) : "r"(hbuf_u32), "r"(p));

    int cur = 0;
    for (int t = 0; t < TT; ++t) {
        float xw = 0.0f;
        if (tid < 256) xw = outp[(size_t)t * HH];   // prefetch xwx

        const float* hc = hbuf + cur * (BATCH_PER_CL * HH);
        unsigned long long a01[4] = {0ULL, 0ULL, 0ULL, 0ULL};
        unsigned long long a23[4] = {0ULL, 0ULL, 0ULL, 0ULL};

#pragma unroll
        for (int kk4 = 0; kk4 < 4; ++kk4) {
            const int k = kbase + kk4 * 4;
#pragma unroll
            for (int b = 0; b < 4; ++b) {
                float4 hv = *reinterpret_cast<const float4*>(&hc[b * HH + k]);
                unsigned long long hh;
                hh = pack_dup(hv.x);
                ffma2(a01[b], hh, w01[kk4 * 4 + 0]);
                ffma2(a23[b], hh, w23[kk4 * 4 + 0]);
                hh = pack_dup(hv.y);
                ffma2(a01[b], hh, w01[kk4 * 4 + 1]);
                ffma2(a23[b], hh, w23[kk4 * 4 + 1]);
                hh = pack_dup(hv.z);
                ffma2(a01[b], hh, w01[kk4 * 4 + 2]);
                ffma2(a23[b], hh, w23[kk4 * 4 + 2]);
                hh = pack_dup(hv.w);
                ffma2(a01[b], hh, w01[kk4 * 4 + 3]);
                ffma2(a23[b], hh, w23[kk4 * 4 + 3]);
            }
        }

        // partials -> red[kq][b][4cq..4cq+3] (contiguous 512B per half-warp)
#pragma unroll
        for (int b = 0; b < 4; ++b) {
            ulonglong2 v;
            v.x = a01[b];
            v.y = a23[b];
            *reinterpret_cast<ulonglong2*>(
                &red[(kq * BATCH_PER_CL + b) * COLS_PER_CTA + cq * 4]) = v;
        }
        __syncthreads();

        if (tid < 256) {
            // 32-way reduce, 4 parallel chains
            float s0 = xw, s1 = 0.f, s2 = 0.f, s3 = 0.f;
#pragma unroll
            for (int q = 0; q < 8; ++q) {
                s0 += red[((4 * q + 0) * BATCH_PER_CL + fb) * COLS_PER_CTA + fc];
                s1 += red[((4 * q + 1) * BATCH_PER_CL + fb) * COLS_PER_CTA + fc];
                s2 += red[((4 * q + 2) * BATCH_PER_CL + fb) * COLS_PER_CTA + fc];
                s3 += red[((4 * q + 3) * BATCH_PER_CL + fb) * COLS_PER_CTA + fc];
            }
            float s = (s0 + s1) + (s2 + s3);
            float r;
            asm("tanh.approx.f32 %0, %1;" : "=f"(r) : "f"(s));

            outp[(size_t)t * HH] = r;

            const int nxt = cur ^ 1;
            const uint32_t off =
                (uint32_t)((nxt * BATCH_PER_CL + fb) * HH + jg) * 4u;
#pragma unroll
            for (int p = 0; p < CLUSTER; ++p)
                asm volatile("st.shared::cluster.f32 [%0], %1;"
                             :: "r"(rb[p] + off), "f"(r) : "memory");
        }

        asm volatile("barrier.cluster.arrive.aligned;\n\t"
                     "barrier.cluster.wait.aligned;" ::: "memory");
        cur ^= 1;
    }
}

// ---------------------------------------------------------------------------
// Launch: inputs in metadata order: x, h0, Wx, Wh, b. Output (N,T,H) fp32.
// ---------------------------------------------------------------------------
extern "C" void kernel_launch(void* const* d_in, const int* in_sizes, int n_in,
                              void* d_out, int out_size) {
    const float* x  = (const float*)d_in[0];
    const float* h0 = (const float*)d_in[1];
    const float* Wx = (const float*)d_in[2];
    const float* Wh = (const float*)d_in[3];
    const float* b  = (const float*)d_in[4];
    float* out = (float*)d_out;

    (void)in_sizes; (void)n_in; (void)out_size;

    // Stage 1: xwx = x @ Wx + b, into out (scratch).
    dim3 gridA(HH / BN, MM / BM);
    gemm_xwx_kernel<<<gridA, 256>>>(x, Wx, b, out);

    // Stage 2: register-resident-Wh cluster recurrence.
    cudaFuncSetAttribute(rnn_cluster_kernel,
                         cudaFuncAttributeMaxDynamicSharedMemorySize,
                         RNN_SMEM_BYTES);
    rnn_cluster_kernel<<<NCTA, 512, RNN_SMEM_BYTES>>>(h0, Wh, out);
}

// round 7
// speedup vs baseline: 9.0975x; 1.1156x over previous
#include <cuda_runtime.h>
#include <cuda_bf16.h>
#include <math.h>
#include <stdint.h>

// Problem constants: N=64, T=512, D=512, H=512, fp32
#define NB   64
#define TT   512
#define DD   512
#define HH   512
#define MM   (NB * TT)

// ---------------------------------------------------------------------------
// f32x2 packed-math helpers
// ---------------------------------------------------------------------------
__device__ __forceinline__ void ffma2(unsigned long long& acc,
                                      unsigned long long a,
                                      unsigned long long b) {
    asm("fma.rn.f32x2 %0, %1, %2, %0;" : "+l"(acc) : "l"(a), "l"(b));
}
__device__ __forceinline__ unsigned long long add2(unsigned long long a,
                                                   unsigned long long b) {
    unsigned long long r;
    asm("add.rn.f32x2 %0, %1, %2;" : "=l"(r) : "l"(a), "l"(b));
    return r;
}
__device__ __forceinline__ unsigned long long pack_dup(float v) {
    unsigned long long r;
    unsigned u = __float_as_uint(v);
    asm("mov.b64 %0, {%1, %1};" : "=l"(r) : "r"(u));
    return r;
}
__device__ __forceinline__ unsigned long long pack2(float lo, float hi) {
    unsigned long long r;
    asm("mov.b64 %0, {%1, %2};" : "=l"(r) : "f"(lo), "f"(hi));
    return r;
}

// mbarrier helpers -----------------------------------------------------------
#define MBAR_INIT(addr, cnt) \
    asm volatile("mbarrier.init.shared.b64 [%0], %1;" :: "r"(addr), "r"(cnt) : "memory")
#define MBAR_EXPECT_TX(addr, bytes) \
    asm volatile("mbarrier.arrive.expect_tx.shared.b64 _, [%0], %1;" \
                 :: "r"(addr), "r"(bytes) : "memory")
#define MBAR_ARRIVE_REMOTE(addr) \
    asm volatile("mbarrier.arrive.shared::cluster.b64 _, [%0];" :: "r"(addr) : "memory")

__device__ __forceinline__ void mbar_wait_parity(uint32_t mbar, uint32_t parity) {
    asm volatile(
        "{\n\t"
        ".reg .pred P;\n\t"
        "WL_%=:\n\t"
        "mbarrier.try_wait.parity.acquire.cluster.shared::cta.b64 P, [%0], %1, 0x989680;\n\t"
        "@P bra WD_%=;\n\t"
        "bra WL_%=;\n\t"
        "WD_%=:\n\t"
        "}" :: "r"(mbar), "r"(parity) : "memory");
}

__device__ __forceinline__ void st_async_b64(uint32_t raddr, unsigned long long v,
                                             uint32_t rmbar) {
    asm volatile(
        "st.async.shared::cluster.mbarrier::complete_tx::bytes.b64 [%0], %1, [%2];"
        :: "r"(raddr), "l"(v), "r"(rmbar) : "memory");
}

// ---------------------------------------------------------------------------
// Kernel A: xwx = x @ Wx + b  (into d_out), FFMA2 SGEMM
// ---------------------------------------------------------------------------
#define BM 128
#define BN 128
#define BK 8

__global__ __launch_bounds__(256) void gemm_xwx_kernel(
    const float* __restrict__ X,
    const float* __restrict__ Wx,
    const float* __restrict__ bias,
    float* __restrict__ out)
{
    __shared__ float2 Asd[BK][BM];
    __shared__ float  Bs[BK][BN];

    const int tid = threadIdx.x;
    const int m0 = blockIdx.y * BM;
    const int n0 = blockIdx.x * BN;

    const int arow = tid >> 1;
    const int acol = (tid & 1) * 4;
    const int brow = tid >> 5;
    const int bcol = (tid & 31) * 4;

    const int ty = tid >> 4;
    const int tx = tid & 15;

    unsigned long long acc2[8][4];
#pragma unroll
    for (int i = 0; i < 8; ++i)
#pragma unroll
        for (int j = 0; j < 4; ++j) acc2[i][j] = 0ULL;

    for (int k0 = 0; k0 < DD; k0 += BK) {
        float4 av = *reinterpret_cast<const float4*>(
            X + (size_t)(m0 + arow) * DD + k0 + acol);
        float4 bv = *reinterpret_cast<const float4*>(
            Wx + (size_t)(k0 + brow) * HH + n0 + bcol);

        Asd[acol + 0][arow] = make_float2(av.x, av.x);
        Asd[acol + 1][arow] = make_float2(av.y, av.y);
        Asd[acol + 2][arow] = make_float2(av.z, av.z);
        Asd[acol + 3][arow] = make_float2(av.w, av.w);
        *reinterpret_cast<float4*>(&Bs[brow][bcol]) = bv;
        __syncthreads();

#pragma unroll
        for (int k = 0; k < BK; ++k) {
            unsigned long long a2[8], b2[4];
            ulonglong2 t0 = *reinterpret_cast<const ulonglong2*>(&Bs[k][tx * 8]);
            ulonglong2 t1 = *reinterpret_cast<const ulonglong2*>(&Bs[k][tx * 8 + 4]);
            b2[0] = t0.x; b2[1] = t0.y; b2[2] = t1.x; b2[3] = t1.y;
#pragma unroll
            for (int i = 0; i < 8; ++i)
                a2[i] = *reinterpret_cast<const unsigned long long*>(&Asd[k][ty * 8 + i]);
#pragma unroll
            for (int i = 0; i < 8; ++i)
#pragma unroll
                for (int j = 0; j < 4; ++j)
                    ffma2(acc2[i][j], a2[i], b2[j]);
        }
        __syncthreads();
    }

    unsigned long long bb2[4];
    {
        ulonglong2 t0 = *reinterpret_cast<const ulonglong2*>(bias + n0 + tx * 8);
        ulonglong2 t1 = *reinterpret_cast<const ulonglong2*>(bias + n0 + tx * 8 + 4);
        bb2[0] = t0.x; bb2[1] = t0.y; bb2[2] = t1.x; bb2[3] = t1.y;
    }
#pragma unroll
    for (int i = 0; i < 8; ++i) {
        float* orow = out + (size_t)(m0 + ty * 8 + i) * HH + n0 + tx * 8;
        ulonglong2 v0, v1;
        v0.x = add2(acc2[i][0], bb2[0]);
        v0.y = add2(acc2[i][1], bb2[1]);
        v1.x = add2(acc2[i][2], bb2[2]);
        v1.y = add2(acc2[i][3], bb2[3]);
        *reinterpret_cast<ulonglong2*>(orow)     = v0;
        *reinterpret_cast<ulonglong2*>(orow + 4) = v1;
    }
}

// ---------------------------------------------------------------------------
// Kernel B: cluster recurrence, Wh register-resident, mbarrier/st.async
// pipelined h exchange. FIX vs R5: producers skip the empty[q] wait at t==0
// (buffer 1 is empty by construction; waiting on it deadlocks the cluster).
// ---------------------------------------------------------------------------
#define CLUSTER       8
#define NCTA          128
#define BATCH_PER_CL  4
#define COLS_PER_CTA  64

#define HBUF_ELEMS (2 * BATCH_PER_CL * HH)             // 4096 floats
#define RED_ELEMS  (32 * BATCH_PER_CL * COLS_PER_CTA)  // 8192 floats
#define MBAR_OFF   ((HBUF_ELEMS + RED_ELEMS) * 4)      // 49152 bytes
// layout at MBAR_OFF: full0 (+0), empty0 (+8), full1 (+16), empty1 (+24)
#define RNN_SMEM_BYTES (MBAR_OFF + 32)

#define STEP_TX_BYTES (BATCH_PER_CL * HH * 4)          // 8192 per buffer fill

__global__ __launch_bounds__(512, 1) __cluster_dims__(CLUSTER, 1, 1)
void rnn_cluster_kernel(const float* __restrict__ h0,
                        const float* __restrict__ Wh,
                        float* __restrict__ out)
{
    extern __shared__ float smem[];
    float* hbuf = smem;                 // [2][4][HH]
    float* red  = smem + HBUF_ELEMS;    // [32][4][64]

    const int tid = threadIdx.x;
    uint32_t rank;
    asm("mov.u32 %0, %%cluster_ctarank;" : "=r"(rank));
    const int cid = blockIdx.x >> 3;
    const int b0  = cid * BATCH_PER_CL;

    const int kq    = tid >> 4;          // 0..31
    const int cq    = tid & 15;          // 0..15
    const int kbase = kq * 16;
    const int jg0   = (int)rank * COLS_PER_CTA + cq * 4;

    // ---- Wh slice -> registers (once) ----
    unsigned long long w01[16], w23[16];
#pragma unroll
    for (int kk = 0; kk < 16; ++kk) {
        ulonglong2 v = *reinterpret_cast<const ulonglong2*>(
            Wh + (size_t)(kbase + kk) * HH + jg0);
        w01[kk] = v.x;
        w23[kk] = v.y;
    }

    uint32_t smem_u32;
    asm("{ .reg .u64 t; cvta.to.shared.u64 t, %1; cvt.u32.u64 %0, t; }"
        : "=r"(smem_u32) : "l"(smem));
    const uint32_t mb_full[2]  = {smem_u32 + MBAR_OFF + 0,  smem_u32 + MBAR_OFF + 16};
    const uint32_t mb_empty[2] = {smem_u32 + MBAR_OFF + 8,  smem_u32 + MBAR_OFF + 24};

    // ---- init: mbarriers + h0 into buffer 0 ----
    if (tid == 0) {
        MBAR_INIT(mb_full[0], 1);
        MBAR_INIT(mb_full[1], 1);
        MBAR_INIT(mb_empty[0], CLUSTER);
        MBAR_INIT(mb_empty[1], CLUSTER);
        MBAR_EXPECT_TX(mb_full[0], STEP_TX_BYTES);   // pre-arm phase 0
        MBAR_EXPECT_TX(mb_full[1], STEP_TX_BYTES);
    }
    for (int idx = tid; idx < BATCH_PER_CL * HH; idx += 512)
        hbuf[idx] = h0[(size_t)b0 * HH + idx];
    __syncthreads();
    asm volatile("barrier.cluster.arrive.aligned;\n\t"
                 "barrier.cluster.wait.aligned;" ::: "memory");

    // peer smem base addresses (mapa once)
    uint32_t rbase[CLUSTER];
#pragma unroll
    for (int p = 0; p < CLUSTER; ++p)
        asm("mapa.shared::cluster.u32 %0, %1, %2;"
            : "=r"(rbase[p]) : "r"(smem_u32), "r"(p));

    // output-stage mapping (threads < 256)
    const int fb = (tid >> 6) & 3;
    const int fc = tid & 63;
    const int jg = (int)rank * COLS_PER_CTA + fc;
    float* outp = out + ((size_t)(b0 + fb) * TT) * HH + jg;
    const bool is_red   = (tid < 256);
    const bool is_store = (tid < 256) && ((tid & 1) == 0);

    int pf[2] = {0, 0};
    int pe[2] = {0, 0};

#pragma unroll 2
    for (int t = 0; t < TT; ++t) {
        const int p = t & 1;
        const int q = p ^ 1;

        // prefetch xwx for this step (independent of h)
        float xw = 0.0f;
        if (is_red) xw = outp[(size_t)t * HH];

        // wait for h_t to be fully delivered into hbuf[p]
        if (t > 0) {
            mbar_wait_parity(mb_full[p], (uint32_t)pf[p]);
            pf[p] ^= 1;
        }

        const float* hc = hbuf + p * (BATCH_PER_CL * HH);
        unsigned long long a01[4] = {0ULL, 0ULL, 0ULL, 0ULL};
        unsigned long long a23[4] = {0ULL, 0ULL, 0ULL, 0ULL};

#pragma unroll
        for (int kk4 = 0; kk4 < 4; ++kk4) {
            const int k = kbase + kk4 * 4;
#pragma unroll
            for (int b = 0; b < 4; ++b) {
                float4 hv = *reinterpret_cast<const float4*>(&hc[b * HH + k]);
                unsigned long long hh;
                hh = pack_dup(hv.x);
                ffma2(a01[b], hh, w01[kk4 * 4 + 0]);
                ffma2(a23[b], hh, w23[kk4 * 4 + 0]);
                hh = pack_dup(hv.y);
                ffma2(a01[b], hh, w01[kk4 * 4 + 1]);
                ffma2(a23[b], hh, w23[kk4 * 4 + 1]);
                hh = pack_dup(hv.z);
                ffma2(a01[b], hh, w01[kk4 * 4 + 2]);
                ffma2(a23[b], hh, w23[kk4 * 4 + 2]);
                hh = pack_dup(hv.w);
                ffma2(a01[b], hh, w01[kk4 * 4 + 3]);
                ffma2(a23[b], hh, w23[kk4 * 4 + 3]);
            }
        }

        // partials -> red[kq][b][4cq..4cq+3]
#pragma unroll
        for (int b = 0; b < 4; ++b) {
            ulonglong2 v;
            v.x = a01[b];
            v.y = a23[b];
            *reinterpret_cast<ulonglong2*>(
                &red[(kq * BATCH_PER_CL + b) * COLS_PER_CTA + cq * 4]) = v;
        }
        __syncthreads();   // all partials in red; all reads of hbuf[p] done

        if (tid == 0) {
            // re-arm full[p] for its next fill (stores arriving during t+1)
            if (t > 0) MBAR_EXPECT_TX(mb_full[p], STEP_TX_BYTES);
            // signal "this CTA finished reading buffer p" to all 8 CTAs
#pragma unroll
            for (int pp = 0; pp < CLUSTER; ++pp)
                MBAR_ARRIVE_REMOTE(rbase[pp] + MBAR_OFF + 8 + (p << 4));
        }

        float r = 0.0f;
        if (is_red) {
            float s0 = xw, s1 = 0.f, s2 = 0.f, s3 = 0.f;
#pragma unroll
            for (int qd = 0; qd < 8; ++qd) {
                s0 += red[((4 * qd + 0) * BATCH_PER_CL + fb) * COLS_PER_CTA + fc];
                s1 += red[((4 * qd + 1) * BATCH_PER_CL + fb) * COLS_PER_CTA + fc];
                s2 += red[((4 * qd + 2) * BATCH_PER_CL + fb) * COLS_PER_CTA + fc];
                s3 += red[((4 * qd + 3) * BATCH_PER_CL + fb) * COLS_PER_CTA + fc];
            }
            float s = (s0 + s1) + (s2 + s3);
            asm("tanh.approx.f32 %0, %1;" : "=f"(r) : "f"(s));
            outp[(size_t)t * HH] = r;
        }

        if (t + 1 < TT) {
            // pair adjacent columns for 8-byte remote stores
            float rn = __shfl_down_sync(0xFFFFFFFFu, r, 1);
            if (is_store) {
                unsigned long long v = pack2(r, rn);
                // Buffer q was last read at step t-1; at t==0 it has never
                // been read (and never will have been) -> no wait needed.
                // Waiting here at t==0 deadlocks the cluster (R5 bug).
                if (t > 0) {
                    mbar_wait_parity(mb_empty[q], (uint32_t)pe[q]);
                    pe[q] ^= 1;
                }
                const uint32_t off =
                    (uint32_t)((q * BATCH_PER_CL + fb) * HH + jg) * 4u;
                const uint32_t mboff = MBAR_OFF + (q << 4);
#pragma unroll
                for (int pp = 0; pp < CLUSTER; ++pp)
                    st_async_b64(rbase[pp] + off, v, rbase[pp] + mboff);
            }
        }
        __syncthreads();   // protect red for next step's partial stores
    }

    // drain before exit
    asm volatile("barrier.cluster.arrive.aligned;\n\t"
                 "barrier.cluster.wait.aligned;" ::: "memory");
}

// ---------------------------------------------------------------------------
// Launch
// ---------------------------------------------------------------------------
extern "C" void kernel_launch(void* const* d_in, const int* in_sizes, int n_in,
                              void* d_out, int out_size) {
    const float* x  = (const float*)d_in[0];
    const float* h0 = (const float*)d_in[1];
    const float* Wx = (const float*)d_in[2];
    const float* Wh = (const float*)d_in[3];
    const float* b  = (const float*)d_in[4];
    float* out = (float*)d_out;

    (void)in_sizes; (void)n_in; (void)out_size;

    dim3 gridA(HH / BN, MM / BM);
    gemm_xwx_kernel<<<gridA, 256>>>(x, Wx, b, out);

    cudaFuncSetAttribute(rnn_cluster_kernel,
                         cudaFuncAttributeMaxDynamicSharedMemorySize,
                         RNN_SMEM_BYTES);
    rnn_cluster_kernel<<<NCTA, 512, RNN_SMEM_BYTES>>>(h0, Wh, out);
}